// round 2
// baseline (speedup 1.0000x reference)
#include <cuda_runtime.h>
#include <cuda_bf16.h>

// KAN_6597069767329: per-input-feature cubic B-spline least squares.
//   x    [N,64] f32, y [N,64,16] f32, grid [64,15] f32 (uniform, hardcoded)
//   out  [16,64,11] f32 :  out[o,i,k] = solve(A_i^T A_i, A_i^T B_i)[k,o]

#define IN_F   64
#define OUT_F  16
#define KB     11
#define NCHUNK 16
#define TILE   128
#define NMAX   100352

typedef unsigned long long ull;

__device__ float g_xT[IN_F * NMAX];                      // transposed x
__device__ float g_pAtB[IN_F * NCHUNK * 12 * OUT_F];     // partial AtB (k padded to 12)
__device__ float g_pAtA[IN_F * NCHUNK * 66];             // partial AtA triangle

// ---- packed f32x2 helpers -------------------------------------------------
__device__ __forceinline__ void fma2(ull &acc, ull a, ull b) {
    asm("fma.rn.f32x2 %0, %1, %2, %0;" : "+l"(acc) : "l"(a), "l"(b));
}
__device__ __forceinline__ ull bcast2(float v) {
    ull r; unsigned int u = __float_as_uint(v);
    asm("mov.b64 %0, {%1, %1};" : "=l"(r) : "r"(u));
    return r;
}
__device__ __forceinline__ ull wred2(ull v) {
#pragma unroll
    for (int m = 16; m > 0; m >>= 1) {
        ull o = __shfl_xor_sync(0xffffffffu, v, m);
        asm("add.rn.f32x2 %0, %0, %1;" : "+l"(v) : "l"(o));
    }
    return v;
}
__device__ __forceinline__ float wredf(float v) {
#pragma unroll
    for (int m = 16; m > 0; m >>= 1)
        v += __shfl_xor_sync(0xffffffffu, v, m);
    return v;
}

// ---- phase 0: transpose x [N,64] -> xT [64,N] -----------------------------
__global__ void transpose_kernel(const float* __restrict__ x, int N) {
    __shared__ float tile[32][33];
    int n0 = blockIdx.x * 32;
    int c0 = blockIdx.y * 32;
#pragma unroll
    for (int r = 0; r < 4; r++) {
        int row = threadIdx.y + r * 8;
        int n = n0 + row;
        if (n < N) tile[row][threadIdx.x] = x[(size_t)n * IN_F + c0 + threadIdx.x];
    }
    __syncthreads();
#pragma unroll
    for (int r = 0; r < 4; r++) {
        int f = threadIdx.y + r * 8;
        int n = n0 + threadIdx.x;
        if (n < N) g_xT[(size_t)(c0 + f) * N + n] = tile[threadIdx.x][f];
    }
}

// cardinal uniform cubic B-spline: 4 nonzero weights at columns j..j+3
__device__ __forceinline__ void write_basis(float* row, float xv) {
    float t = (xv + 1.0f) * 4.0f;            // maps [-1,1] -> [0,8]
    int j = (int)floorf(t);
    j = max(0, min(7, j));
    float u = t - (float)j;
    float um = 1.0f - u;
    float u2 = u * u, u3 = u2 * u;
    float um3 = um * um * um;
    const float c6 = 1.0f / 6.0f;
    row[j]     = um3 * c6;
    row[j + 1] = (3.0f * u3 - 6.0f * u2 + 4.0f) * c6;
    row[j + 2] = (-3.0f * u3 + 3.0f * u2 + 3.0f * u + 1.0f) * c6;
    row[j + 3] = u3 * c6;
}

// AtA triangle accumulation over compile-time pair range [LO, HI)
template <int LO, int HI>
__device__ __forceinline__ void ata_range(const float* b, float* acc) {
    int p = 0;
#pragma unroll
    for (int ka = 0; ka < KB; ka++) {
#pragma unroll
        for (int kb = ka; kb < KB; kb++) {
            if (p >= LO && p < HI)
                acc[p - LO] += b[ka] * b[kb];
            p++;
        }
    }
}

// ---- phase 1: accumulate AtA / AtB partials per (feature, chunk) ----------
__global__ __launch_bounds__(288) void accum_kernel(const float* __restrict__ y, int N) {
    const int feat  = blockIdx.y;     // 0..63
    const int chunk = blockIdx.x;     // 0..NCHUNK-1
    const int t = threadIdx.x;
    const int warp = t >> 5, lane = t & 31;

    __shared__ float Bs[TILE * 14];   // basis rows, 12 cols (pad k=11) stride 14
    __shared__ float Ys[TILE * 20];   // y rows, 16 cols, stride 20

    const int per  = (N + NCHUNK - 1) / NCHUNK;
    const int s_lo = chunk * per;
    const int s_hi = min(N, s_lo + per);

    ull accB[2][8];                   // AtB: warps 0..5, k rows {2w,2w+1}, 16 outs
#pragma unroll
    for (int a = 0; a < 2; a++)
#pragma unroll
        for (int q = 0; q < 8; q++) accB[a][q] = 0ull;
    float accA[22];                   // AtA: warps 6..8, 22 pairs each
#pragma unroll
    for (int p = 0; p < 22; p++) accA[p] = 0.f;

    const float* xT = g_xT + (size_t)feat * N;

    for (int base = s_lo; base < s_hi; base += TILE) {
        // ---- stage basis ----
        if (t < TILE) {
            float* row = Bs + t * 14;
            float2 z2 = make_float2(0.f, 0.f);
#pragma unroll
            for (int q = 0; q < 6; q++) ((float2*)row)[q] = z2;
            int s = base + t;
            if (s < s_hi) write_basis(row, xT[s]);
        }
        // ---- stage y: 128 samples x 4 float4 ----
        for (int idx = t; idx < TILE * 4; idx += 288) {
            int sloc = idx >> 2;
            int quad = idx & 3;
            int s = base + sloc;
            float4 val = make_float4(0.f, 0.f, 0.f, 0.f);
            if (s < s_hi)
                val = *(const float4*)(y + ((size_t)s * IN_F + feat) * OUT_F + quad * 4);
            *(float4*)(Ys + sloc * 20 + quad * 4) = val;
        }
        __syncthreads();

        if (warp < 6) {
            const int k2 = warp * 2;
#pragma unroll
            for (int j = 0; j < 4; j++) {
                int s = lane + 32 * j;
                float2 b = *(const float2*)(Bs + s * 14 + k2);
                ull b0 = bcast2(b.x), b1 = bcast2(b.y);
                const ulonglong2* yp = (const ulonglong2*)(Ys + s * 20);
#pragma unroll
                for (int h = 0; h < 2; h++) {
                    ulonglong2 yv = yp[h * 2];
                    ulonglong2 yw = yp[h * 2 + 1];
                    fma2(accB[0][4 * h + 0], b0, yv.x);
                    fma2(accB[0][4 * h + 1], b0, yv.y);
                    fma2(accB[0][4 * h + 2], b0, yw.x);
                    fma2(accB[0][4 * h + 3], b0, yw.y);
                    fma2(accB[1][4 * h + 0], b1, yv.x);
                    fma2(accB[1][4 * h + 1], b1, yv.y);
                    fma2(accB[1][4 * h + 2], b1, yw.x);
                    fma2(accB[1][4 * h + 3], b1, yw.y);
                }
            }
        } else {
            const int grp = warp - 6;     // 0..2
#pragma unroll
            for (int j = 0; j < 4; j++) {
                int s = lane + 32 * j;
                float b[12];
#pragma unroll
                for (int q = 0; q < 6; q++) {
                    float2 v = *(const float2*)(Bs + s * 14 + 2 * q);
                    b[2 * q] = v.x; b[2 * q + 1] = v.y;
                }
                if      (grp == 0) ata_range<0, 22>(b, accA);
                else if (grp == 1) ata_range<22, 44>(b, accA);
                else               ata_range<44, 66>(b, accA);
            }
        }
        __syncthreads();
    }

    // ---- deterministic warp reductions + write partials ----
    if (warp < 6) {
#pragma unroll
        for (int a = 0; a < 2; a++)
#pragma unroll
            for (int q = 0; q < 8; q++) accB[a][q] = wred2(accB[a][q]);
        if (lane == 0) {
            size_t b0 = (((size_t)feat * NCHUNK + chunk) * 12 + 2 * warp) * OUT_F;
#pragma unroll
            for (int a = 0; a < 2; a++)
#pragma unroll
                for (int q = 0; q < 8; q++)
                    *(ull*)(g_pAtB + b0 + a * OUT_F + 2 * q) = accB[a][q];
        }
    } else {
        const int grp = warp - 6;
        const int lo = grp * 22;
        size_t b0 = ((size_t)feat * NCHUNK + chunk) * 66 + lo;
#pragma unroll
        for (int p = 0; p < 22; p++) {
            float v = wredf(accA[p]);
            if (lane == 0) g_pAtA[b0 + p] = v;
        }
    }
}

// triangle index for pair (a <= b), matching ata_range enumeration
__device__ __forceinline__ int tidx(int a, int b) {
    return a * KB - (a * (a - 1)) / 2 + (b - a);
}

// ---- phase 2: reduce partials, double Cholesky solve, write output --------
__global__ void solve_kernel(float* __restrict__ out) {
    const int i = blockIdx.x;   // feature
    const int t = threadIdx.x;
    __shared__ double sAtA[66];
    __shared__ double sL[66];
    __shared__ double sAtB[KB][OUT_F];

    for (int p = t; p < 66; p += 128) {
        double s = 0.0;
        for (int c = 0; c < NCHUNK; c++)
            s += (double)g_pAtA[((size_t)i * NCHUNK + c) * 66 + p];
        sAtA[p] = s;
    }
    for (int e = t; e < KB * OUT_F; e += 128) {
        int k = e / OUT_F, o = e % OUT_F;
        double s = 0.0;
        for (int c = 0; c < NCHUNK; c++)
            s += (double)g_pAtB[(((size_t)i * NCHUNK + c) * 12 + k) * OUT_F + o];
        sAtB[k][o] = s;
    }
    __syncthreads();

    if (t == 0) {
        for (int j = 0; j < KB; j++) {
            double d = sAtA[tidx(j, j)];
            for (int m = 0; m < j; m++) { double v = sL[tidx(m, j)]; d -= v * v; }
            d = sqrt(d);
            sL[tidx(j, j)] = d;
            double inv = 1.0 / d;
            for (int r = j + 1; r < KB; r++) {
                double s = sAtA[tidx(j, r)];
                for (int m = 0; m < j; m++) s -= sL[tidx(m, r)] * sL[tidx(m, j)];
                sL[tidx(j, r)] = s * inv;
            }
        }
    }
    __syncthreads();

    if (t < OUT_F) {
        const int o = t;
        double z[KB], X[KB];
        for (int r = 0; r < KB; r++) {
            double s = sAtB[r][o];
            for (int m = 0; m < r; m++) s -= sL[tidx(m, r)] * z[m];
            z[r] = s / sL[tidx(r, r)];
        }
        for (int r = KB - 1; r >= 0; r--) {
            double s = z[r];
            for (int m = r + 1; m < KB; m++) s -= sL[tidx(r, m)] * X[m];
            X[r] = s / sL[tidx(r, r)];
            out[(size_t)o * (IN_F * KB) + i * KB + r] = (float)X[r];
        }
    }
}

extern "C" void kernel_launch(void* const* d_in, const int* in_sizes, int n_in,
                              void* d_out, int out_size) {
    const float* x = (const float*)d_in[0];
    const float* y = (const float*)d_in[1];
    (void)n_in; (void)out_size;
    float* out = (float*)d_out;
    int N = in_sizes[0] / IN_F;

    dim3 tgrid((N + 31) / 32, IN_F / 32);
    transpose_kernel<<<tgrid, dim3(32, 8)>>>(x, N);

    dim3 agrid(NCHUNK, IN_F);
    accum_kernel<<<agrid, 288>>>(y, N);

    solve_kernel<<<IN_F, 128>>>(out);
}

// round 3
// speedup vs baseline: 2.8413x; 2.8413x over previous
#include <cuda_runtime.h>
#include <cuda_bf16.h>
#include <stdint.h>

// KAN_6597069767329: per-input-feature cubic B-spline least squares.
//   x [N,64] f32, y [N,64,16] f32, grid [64,15] f32 (uniform, hardcoded)
//   out [16,64,11] f32 : out[o,i,k] = solve(A_i^T A_i, A_i^T B_i)[k,o]

#define IN_F   64
#define OUT_F  16
#define KB     11
#define NCH    7
#define TILE   256
#define NMAX   100352

typedef unsigned long long ull;

__device__ float g_xT[IN_F * NMAX];
// [feat][chunk][qj][ohalf][oo(8)][k(12)]
__device__ float g_pAtB[IN_F * NCH * 4 * 2 * 8 * 12];
// [feat][chunk][j*7+p]
__device__ float g_pMom[IN_F * NCH * 56];

// ---- smem layout (floats) -------------------------------------------------
#define YS_STRIDE 20
#define YS_BUF    (TILE * YS_STRIDE)          // 5120
#define BS_OFF    (3 * YS_BUF)                // 15360
#define BS_STRIDE 14
#define BS_BUF    (TILE * BS_STRIDE)          // 3584
#define MOM_OFF   (BS_OFF + 2 * BS_BUF)       // 22528
#define MOM_STRIDE 57
#define SMEM_FLOATS (MOM_OFF + TILE * MOM_STRIDE)   // 37120 floats = 148480 B

// ---- helpers --------------------------------------------------------------
__device__ __forceinline__ void fma2(ull &acc, ull a, ull b) {
    asm("fma.rn.f32x2 %0, %1, %2, %0;" : "+l"(acc) : "l"(a), "l"(b));
}
__device__ __forceinline__ ull bcast2(float v) {
    ull r; unsigned int u = __float_as_uint(v);
    asm("mov.b64 %0, {%1, %1};" : "=l"(r) : "r"(u));
    return r;
}
__device__ __forceinline__ ull wred2(ull v) {
#pragma unroll
    for (int m = 16; m > 0; m >>= 1) {
        ull o = __shfl_xor_sync(0xffffffffu, v, m);
        asm("add.rn.f32x2 %0, %0, %1;" : "+l"(v) : "l"(o));
    }
    return v;
}
__device__ __forceinline__ unsigned smem_u32(const void* p) {
    return (unsigned)__cvta_generic_to_shared(p);
}
__device__ __forceinline__ void cp16(unsigned dst, const void* src) {
    asm volatile("cp.async.cg.shared.global [%0], [%1], 16;" :: "r"(dst), "l"(src));
}
__device__ __forceinline__ void cp_commit() {
    asm volatile("cp.async.commit_group;");
}
__device__ __forceinline__ void cp_wait1() {
    asm volatile("cp.async.wait_group 1;");
}

// ---- phase 0: transpose x [N,64] -> xT [64,N] -----------------------------
__global__ void transpose_kernel(const float* __restrict__ x, int N) {
    __shared__ float tile[32][33];
    int n0 = blockIdx.x * 32;
    int c0 = blockIdx.y * 32;
#pragma unroll
    for (int r = 0; r < 4; r++) {
        int row = threadIdx.y + r * 8;
        int n = n0 + row;
        if (n < N) tile[row][threadIdx.x] = x[(size_t)n * IN_F + c0 + threadIdx.x];
    }
    __syncthreads();
#pragma unroll
    for (int r = 0; r < 4; r++) {
        int f = threadIdx.y + r * 8;
        int n = n0 + threadIdx.x;
        if (n < N) g_xT[(size_t)(c0 + f) * N + n] = tile[threadIdx.x][f];
    }
}

// ---- phase 1: AtB accumulation + moment accumulation ----------------------
__global__ __launch_bounds__(256, 1) void accum_kernel(const float* __restrict__ y, int N) {
    extern __shared__ float sm[];
    float* Ys  = sm;                 // 3 bufs of [256][20]
    float* Bs  = sm + BS_OFF;        // 2 bufs of [256][14]
    float* Mom = sm + MOM_OFF;       // [256][57] per-thread moment slices

    const int feat  = blockIdx.y;
    const int chunk = blockIdx.x;
    const int t = threadIdx.x;
    const int warp = t >> 5, lane = t & 31;
    const int ohalf = warp >> 2;     // 0,1
    const int qj    = warp & 3;      // sample quarter

    const int per  = (N + NCH - 1) / NCH;
    const int s_lo = chunk * per;
    const int s_hi = min(N, s_lo + per);
    const int nt   = (s_hi - s_lo + TILE - 1) / TILE;

    const float* xT = g_xT + (size_t)feat * N;
    float* mymom = Mom + t * MOM_STRIDE;
#pragma unroll
    for (int p = 0; p < 56; p++) mymom[p] = 0.f;

    const unsigned ys_u32 = smem_u32(Ys);

    // acc[kp][o]: k-pair kp (k=2kp,2kp+1), output o within half. 48 packed accs.
    ull acc[48];
#pragma unroll
    for (int q = 0; q < 48; q++) acc[q] = 0ull;

    // ---- staging lambdas (plain functions via macros for clarity) ----
    // stage basis for tile ti into buffer bb; also accumulate moments
    auto stage_basis = [&](int ti, int bb) {
        float* row = Bs + bb * BS_BUF + t * BS_STRIDE;
        float2 z2 = make_float2(0.f, 0.f);
#pragma unroll
        for (int q = 0; q < 6; q++) ((float2*)row)[q] = z2;
        int s = s_lo + ti * TILE + t;
        if (s < s_hi) {
            float xv = __ldg(xT + s);
            float tt = (xv + 1.0f) * 4.0f;
            int j = (int)floorf(tt);
            j = max(0, min(7, j));
            float u = tt - (float)j;
            float um = 1.0f - u;
            float u2 = u * u, u3 = u2 * u;
            float um3 = um * um * um;
            const float c6 = 1.0f / 6.0f;
            row[j]     = um3 * c6;
            row[j + 1] = (3.0f * u3 - 6.0f * u2 + 4.0f) * c6;
            row[j + 2] = (-3.0f * u3 + 3.0f * u2 + 3.0f * u + 1.0f) * c6;
            row[j + 3] = u3 * c6;
            float* mslot = mymom + j * 7;
            float up = 1.0f;
#pragma unroll
            for (int p = 0; p < 7; p++) { mslot[p] += up; up *= u; }
        }
    };
    // issue async y loads for tile ti into ring buffer b3
    auto issue_y = [&](int ti, int b3) {
        int s0 = s_lo + ti * TILE;
#pragma unroll
        for (int e = t; e < TILE * 4; e += 256) {
            int sloc = e >> 2, quad = e & 3;
            int s = s0 + sloc;
            float* dstp = Ys + b3 * YS_BUF + sloc * YS_STRIDE + quad * 4;
            if (s < s_hi)
                cp16(smem_u32(dstp), y + ((size_t)s * IN_F + feat) * OUT_F + quad * 4);
            else
                *(float4*)dstp = make_float4(0.f, 0.f, 0.f, 0.f);
        }
    };

    // ---- prolog ----
    stage_basis(0, 0);
    issue_y(0, 0); cp_commit();
    if (nt > 1) issue_y(1, 1);
    cp_commit();

    // ---- main pipeline ----
    for (int i = 0; i < nt; i++) {
        const int b3 = i % 3, b2 = i & 1;
        cp_wait1();
        __syncthreads();
        if (i + 2 < nt) issue_y(i + 2, (i + 2) % 3);
        cp_commit();

        // consume tile i
        const float* BsC = Bs + b2 * BS_BUF;
        const float* YsC = Ys + b3 * YS_BUF;
#pragma unroll
        for (int jj = 0; jj < 2; jj++) {
            int sl = qj * 64 + jj * 32 + lane;
            const float* brow = BsC + sl * BS_STRIDE;
            const float4* yrow = (const float4*)(YsC + sl * YS_STRIDE + ohalf * 8);
            float4 ya = yrow[0];
            float4 yb = yrow[1];
            ull b2v[6];
#pragma unroll
            for (int kp = 0; kp < 6; kp++)
                b2v[kp] = *(const ull*)(brow + 2 * kp);
            ull yB[8];
            yB[0] = bcast2(ya.x); yB[1] = bcast2(ya.y);
            yB[2] = bcast2(ya.z); yB[3] = bcast2(ya.w);
            yB[4] = bcast2(yb.x); yB[5] = bcast2(yb.y);
            yB[6] = bcast2(yb.z); yB[7] = bcast2(yb.w);
#pragma unroll
            for (int kp = 0; kp < 6; kp++)
#pragma unroll
                for (int o = 0; o < 8; o++)
                    fma2(acc[kp * 8 + o], b2v[kp], yB[o]);
        }

        // stage basis for tile i+1 (other buffer)
        if (i + 1 < nt) stage_basis(i + 1, (i + 1) & 1);
    }
    __syncthreads();

    // ---- reduce + write AtB partials ----
#pragma unroll
    for (int q = 0; q < 48; q++) acc[q] = wred2(acc[q]);
    if (lane == 0) {
        size_t base = ((((size_t)feat * NCH + chunk) * 4 + qj) * 2 + ohalf) * 8 * 12;
#pragma unroll
        for (int o = 0; o < 8; o++)
#pragma unroll
            for (int kp = 0; kp < 6; kp++)
                *(ull*)(g_pAtB + base + o * 12 + 2 * kp) = acc[kp * 8 + o];
    }

    // ---- reduce moments across threads (fixed order -> deterministic) ----
    for (int slot = t; slot < 56; slot += 256) {
        float s = 0.f;
        for (int th = 0; th < 256; th++)
            s += Mom[th * MOM_STRIDE + slot];
        g_pMom[((size_t)feat * NCH + chunk) * 56 + slot] = s;
    }
}

// triangle index (a <= b)
__device__ __forceinline__ int tidx(int a, int b) {
    return a * KB - (a * (a - 1)) / 2 + (b - a);
}

// cardinal cubic weight poly coefs (x6): w_a(u) = (1/6) * sum_p CAD[a][p] u^p
__device__ __constant__ double CAD[4][4] = {
    {1.0, -3.0, 3.0, -1.0},
    {4.0,  0.0, -6.0, 3.0},
    {1.0,  3.0,  3.0, -3.0},
    {0.0,  0.0,  0.0,  1.0}
};

// ---- phase 2: reduce partials, build AtA from moments, Cholesky solve -----
__global__ void solve_kernel(float* __restrict__ out) {
    const int i = blockIdx.x;   // feature
    const int t = threadIdx.x;  // 128 threads
    __shared__ double sAtB[12][OUT_F];
    __shared__ double sS[56];
    __shared__ double sAtA[66];
    __shared__ double sL[66];

    // sum AtB partials over (chunk, qj)
    for (int e = t; e < 12 * OUT_F; e += 128) {
        int k = e % 12, o = e / 12;
        int oh = o >> 3, oo = o & 7;
        double s = 0.0;
        for (int c = 0; c < NCH; c++)
            for (int q = 0; q < 4; q++)
                s += (double)g_pAtB[(((((size_t)i * NCH + c) * 4 + q) * 2 + oh) * 8 + oo) * 12 + k];
        sAtB[k][o] = s;
    }
    // sum moments over chunks
    for (int p = t; p < 56; p += 128) {
        double s = 0.0;
        for (int c = 0; c < NCH; c++)
            s += (double)g_pMom[((size_t)i * NCH + c) * 56 + p];
        sS[p] = s;
    }
    __syncthreads();

    // build AtA upper triangle from moments
    if (t < 66) {
        int p = t, r = 0;
        while (p >= KB - r) { p -= KB - r; r++; }
        int cc = r + p;
        double val = 0.0;
        for (int j = 0; j < 8; j++) {
            int a = r - j, b = cc - j;
            if (a >= 0 && a < 4 && b >= 0 && b < 4) {
                for (int p1 = 0; p1 < 4; p1++)
                    for (int q1 = 0; q1 < 4; q1++)
                        val += CAD[a][p1] * CAD[b][q1] * sS[j * 7 + p1 + q1];
            }
        }
        sAtA[t] = val / 36.0;
    }
    __syncthreads();

    if (t == 0) {
        for (int j = 0; j < KB; j++) {
            double d = sAtA[tidx(j, j)];
            for (int m = 0; m < j; m++) { double v = sL[tidx(m, j)]; d -= v * v; }
            d = sqrt(d);
            sL[tidx(j, j)] = d;
            double inv = 1.0 / d;
            for (int r = j + 1; r < KB; r++) {
                double s = sAtA[tidx(j, r)];
                for (int m = 0; m < j; m++) s -= sL[tidx(m, r)] * sL[tidx(m, j)];
                sL[tidx(j, r)] = s * inv;
            }
        }
    }
    __syncthreads();

    if (t < OUT_F) {
        const int o = t;
        double z[KB], X[KB];
        for (int r = 0; r < KB; r++) {
            double s = sAtB[r][o];
            for (int m = 0; m < r; m++) s -= sL[tidx(m, r)] * z[m];
            z[r] = s / sL[tidx(r, r)];
        }
        for (int r = KB - 1; r >= 0; r--) {
            double s = z[r];
            for (int m = r + 1; m < KB; m++) s -= sL[tidx(r, m)] * X[m];
            X[r] = s / sL[tidx(r, r)];
            out[(size_t)o * (IN_F * KB) + i * KB + r] = (float)X[r];
        }
    }
}

extern "C" void kernel_launch(void* const* d_in, const int* in_sizes, int n_in,
                              void* d_out, int out_size) {
    const float* x = (const float*)d_in[0];
    const float* y = (const float*)d_in[1];
    (void)n_in; (void)out_size;
    float* out = (float*)d_out;
    int N = in_sizes[0] / IN_F;

    cudaFuncSetAttribute(accum_kernel,
                         cudaFuncAttributeMaxDynamicSharedMemorySize,
                         SMEM_FLOATS * (int)sizeof(float));

    dim3 tgrid((N + 31) / 32, IN_F / 32);
    transpose_kernel<<<tgrid, dim3(32, 8)>>>(x, N);

    dim3 agrid(NCH, IN_F);
    accum_kernel<<<agrid, 256, SMEM_FLOATS * (int)sizeof(float)>>>(y, N);

    solve_kernel<<<IN_F, 128>>>(out);
}

// round 4
// speedup vs baseline: 2.9280x; 1.0305x over previous
#include <cuda_runtime.h>
#include <cuda_bf16.h>
#include <stdint.h>

// KAN_6597069767329: per-input-feature cubic B-spline least squares.
//   x [N,64] f32, y [N,64,16] f32, grid uniform (hardcoded)
//   out [16,64,11] f32 : out[o,i,k] = solve(A_i^T A_i, A_i^T B_i)[k,o]

#define IN_F   64
#define OUT_F  16
#define KB     11
#define NCH    37            // 32 pairs * 37 = 1184 = 8 * 148 SMs exactly
#define MCH    8             // moment chunks
#define TILE   256
#define NMAX   100352

typedef unsigned long long ull;

__device__ float g_xT[IN_F * NMAX];
// [feat][chunk][sh(2)][oh(2)][o(8)][k(12)]
__device__ float g_pAtB[IN_F * NCH * 2 * 2 * 8 * 12];
// [feat][mchunk][56]
__device__ float g_pMom[IN_F * MCH * 56];

// ---- smem layout (floats) for accum ----------------------------------------
#define YS_STRIDE 36
#define YS_BUF    (TILE * YS_STRIDE)            // 9216 floats
#define BS_OFF    (3 * YS_BUF)                  // 27648
#define BS_STRIDE 14
#define BS_FEAT   (TILE * BS_STRIDE)            // 3584
#define BS_BUF    (2 * BS_FEAT)                 // 7168 (2 features)
#define SMEM_FLOATS (BS_OFF + 2 * BS_BUF)       // 41984 floats = 167936 B

// ---- helpers ---------------------------------------------------------------
__device__ __forceinline__ void fma2(ull &acc, ull a, ull b) {
    asm("fma.rn.f32x2 %0, %1, %2, %0;" : "+l"(acc) : "l"(a), "l"(b));
}
__device__ __forceinline__ ull bcast2(float v) {
    ull r; unsigned int u = __float_as_uint(v);
    asm("mov.b64 %0, {%1, %1};" : "=l"(r) : "r"(u));
    return r;
}
__device__ __forceinline__ ull wred2(ull v) {
#pragma unroll
    for (int m = 16; m > 0; m >>= 1) {
        ull o = __shfl_xor_sync(0xffffffffu, v, m);
        asm("add.rn.f32x2 %0, %0, %1;" : "+l"(v) : "l"(o));
    }
    return v;
}
__device__ __forceinline__ unsigned smem_u32(const void* p) {
    return (unsigned)__cvta_generic_to_shared(p);
}
__device__ __forceinline__ void cp16(unsigned dst, const void* src) {
    asm volatile("cp.async.cg.shared.global [%0], [%1], 16;" :: "r"(dst), "l"(src));
}
__device__ __forceinline__ void cp_commit() {
    asm volatile("cp.async.commit_group;");
}
__device__ __forceinline__ void cp_wait1() {
    asm volatile("cp.async.wait_group 1;");
}

// ---- phase 0: transpose x [N,64] -> xT [64,N] ------------------------------
__global__ void transpose_kernel(const float* __restrict__ x, int N) {
    __shared__ float tile[32][33];
    int n0 = blockIdx.x * 32;
    int c0 = blockIdx.y * 32;
#pragma unroll
    for (int r = 0; r < 4; r++) {
        int row = threadIdx.y + r * 8;
        int n = n0 + row;
        if (n < N) tile[row][threadIdx.x] = x[(size_t)n * IN_F + c0 + threadIdx.x];
    }
    __syncthreads();
#pragma unroll
    for (int r = 0; r < 4; r++) {
        int f = threadIdx.y + r * 8;
        int n = n0 + threadIdx.x;
        if (n < N) g_xT[(size_t)(c0 + f) * N + n] = tile[threadIdx.x][f];
    }
}

// ---- phase 0b: per-cell u-power moments (for AtA reconstruction) ----------
__global__ __launch_bounds__(256) void moments_kernel(int N) {
    const int chunk = blockIdx.x;       // 0..MCH-1
    const int feat  = blockIdx.y;       // 0..63
    const int t = threadIdx.x;
    const int warp = t >> 5, lane = t & 31;

    const int per  = (N + MCH - 1) / MCH;
    const int s_lo = chunk * per;
    const int s_hi = min(N, s_lo + per);

    float mom[8][7];
#pragma unroll
    for (int jc = 0; jc < 8; jc++)
#pragma unroll
        for (int p = 0; p < 7; p++) mom[jc][p] = 0.f;

    const float* xT = g_xT + (size_t)feat * N;
    for (int s = s_lo + t; s < s_hi; s += 256) {
        float xv = __ldg(xT + s);
        float tt = (xv + 1.0f) * 4.0f;
        int j = (int)floorf(tt);
        j = max(0, min(7, j));
        float u = tt - (float)j;
        float up[7];
        up[0] = 1.f;
#pragma unroll
        for (int p = 1; p < 7; p++) up[p] = up[p - 1] * u;
#pragma unroll
        for (int jc = 0; jc < 8; jc++) {
            float sel = (jc == j) ? 1.f : 0.f;
#pragma unroll
            for (int p = 0; p < 7; p++) mom[jc][p] += sel * up[p];
        }
    }

    // warp shfl reduce (fixed order), then cross-warp fixed-order sum
    __shared__ float red[8 * 57];
#pragma unroll
    for (int jc = 0; jc < 8; jc++)
#pragma unroll
        for (int p = 0; p < 7; p++) {
            float v = mom[jc][p];
#pragma unroll
            for (int m = 16; m > 0; m >>= 1)
                v += __shfl_xor_sync(0xffffffffu, v, m);
            if (lane == 0) red[warp * 57 + jc * 7 + p] = v;
        }
    __syncthreads();
    if (t < 56) {
        float s = 0.f;
#pragma unroll
        for (int w = 0; w < 8; w++) s += red[w * 57 + t];
        g_pMom[((size_t)feat * MCH + chunk) * 56 + t] = s;
    }
}

// ---- phase 1: AtB accumulation (feature pairs, full-line y reads) ----------
__global__ __launch_bounds__(256, 1) void accum_kernel(const float* __restrict__ y, int N) {
    extern __shared__ float sm[];
    float* Ys = sm;                 // 3 bufs [256][36]: [sample][feat*16 + o]
    float* Bs = sm + BS_OFF;        // 2 bufs [2 feat][256][14]

    const int pair  = blockIdx.y;   // 0..31
    const int chunk = blockIdx.x;   // 0..NCH-1
    const int i0 = pair * 2;
    const int t = threadIdx.x;
    const int warp = t >> 5, lane = t & 31;
    const int fw = warp & 1;        // feature within pair
    const int oh = (warp >> 1) & 1; // output half
    const int sh = warp >> 2;       // sample half (0,1)

    const int per  = (N + NCH - 1) / NCH;
    const int s_lo = chunk * per;
    const int s_hi = min(N, s_lo + per);
    const int nt   = (s_hi - s_lo + TILE - 1) / TILE;

    const float* xT0 = g_xT + (size_t)i0 * N;
    const float* xT1 = g_xT + (size_t)(i0 + 1) * N;

    ull acc[48];                    // [kp(6)][o(8)] packed k pairs
#pragma unroll
    for (int q = 0; q < 48; q++) acc[q] = 0ull;

    auto stage_basis = [&](int ti, int bb) {
        float* row0 = Bs + bb * BS_BUF + t * BS_STRIDE;
        float* row1 = row0 + BS_FEAT;
        float2 z2 = make_float2(0.f, 0.f);
#pragma unroll
        for (int q = 0; q < 6; q++) { ((float2*)row0)[q] = z2; ((float2*)row1)[q] = z2; }
        int s = s_lo + ti * TILE + t;
        if (s < s_hi) {
            float xv0 = __ldg(xT0 + s);
            float xv1 = __ldg(xT1 + s);
#pragma unroll
            for (int f = 0; f < 2; f++) {
                float xv = f ? xv1 : xv0;
                float* row = f ? row1 : row0;
                float tt = (xv + 1.0f) * 4.0f;
                int j = (int)floorf(tt);
                j = max(0, min(7, j));
                float u = tt - (float)j;
                float um = 1.0f - u;
                float u2 = u * u, u3 = u2 * u;
                float um3 = um * um * um;
                const float c6 = 1.0f / 6.0f;
                row[j]     = um3 * c6;
                row[j + 1] = (3.0f * u3 - 6.0f * u2 + 4.0f) * c6;
                row[j + 2] = (-3.0f * u3 + 3.0f * u2 + 3.0f * u + 1.0f) * c6;
                row[j + 3] = u3 * c6;
            }
        }
    };
    auto issue_y = [&](int ti, int b3) {
        int s0 = s_lo + ti * TILE;
#pragma unroll
        for (int e = t; e < TILE * 8; e += 256) {
            int sloc = e >> 3, q = e & 7;
            int s = s0 + sloc;
            float* dstp = Ys + b3 * YS_BUF + sloc * YS_STRIDE + q * 4;
            if (s < s_hi)
                cp16(smem_u32(dstp), y + ((size_t)s * IN_F + i0) * OUT_F + q * 4);
            else
                *(float4*)dstp = make_float4(0.f, 0.f, 0.f, 0.f);
        }
    };

    // prolog: basis tile0, y tiles 0 and 1
    stage_basis(0, 0);
    issue_y(0, 0); cp_commit();
    if (nt > 1) issue_y(1, 1);
    cp_commit();

    for (int i = 0; i < nt; i++) {
        const int b3 = i % 3, b2 = i & 1;
        cp_wait1();
        __syncthreads();
        if (i + 2 < nt) issue_y(i + 2, (i + 2) % 3);
        cp_commit();

        const float* BsC = Bs + b2 * BS_BUF + fw * BS_FEAT;
        const float* YsC = Ys + b3 * YS_BUF;
#pragma unroll
        for (int jj = 0; jj < 4; jj++) {
            int sl = sh * 128 + jj * 32 + lane;
            const float* brow = BsC + sl * BS_STRIDE;
            const float4* yrow = (const float4*)(YsC + sl * YS_STRIDE + fw * 16 + oh * 8);
            float4 ya = yrow[0];
            float4 yb = yrow[1];
            ull b2v[6];
#pragma unroll
            for (int kp = 0; kp < 6; kp++)
                b2v[kp] = *(const ull*)(brow + 2 * kp);
            ull yB[8];
            yB[0] = bcast2(ya.x); yB[1] = bcast2(ya.y);
            yB[2] = bcast2(ya.z); yB[3] = bcast2(ya.w);
            yB[4] = bcast2(yb.x); yB[5] = bcast2(yb.y);
            yB[6] = bcast2(yb.z); yB[7] = bcast2(yb.w);
#pragma unroll
            for (int kp = 0; kp < 6; kp++)
#pragma unroll
                for (int o = 0; o < 8; o++)
                    fma2(acc[kp * 8 + o], b2v[kp], yB[o]);
        }

        if (i + 1 < nt) stage_basis(i + 1, (i + 1) & 1);
    }

    // reduce + write partials: feat = i0 + fw
#pragma unroll
    for (int q = 0; q < 48; q++) acc[q] = wred2(acc[q]);
    if (lane == 0) {
        size_t base = ((((size_t)(i0 + fw) * NCH + chunk) * 2 + sh) * 2 + oh) * 96;
#pragma unroll
        for (int o = 0; o < 8; o++)
#pragma unroll
            for (int kp = 0; kp < 6; kp++)
                *(ull*)(g_pAtB + base + o * 12 + 2 * kp) = acc[kp * 8 + o];
    }
}

// triangle index (a <= b)
__device__ __forceinline__ int tidx(int a, int b) {
    return a * KB - (a * (a - 1)) / 2 + (b - a);
}

// cardinal cubic weight polys: w_a(u) = (1/6) * sum_p CAD[a][p] u^p
__device__ __constant__ double CAD[4][4] = {
    {1.0, -3.0,  3.0, -1.0},
    {4.0,  0.0, -6.0,  3.0},
    {1.0,  3.0,  3.0, -3.0},
    {0.0,  0.0,  0.0,  1.0}
};

// ---- phase 2: reduce partials, AtA from moments, double Cholesky solve -----
__global__ void solve_kernel(float* __restrict__ out) {
    const int i = blockIdx.x;   // feature
    const int t = threadIdx.x;  // 128 threads
    __shared__ double sAtB[12][OUT_F];
    __shared__ double sS[56];
    __shared__ double sAtA[66];
    __shared__ double sL[66];

    for (int e = t; e < 12 * OUT_F; e += 128) {
        int k = e % 12, o = e / 12;
        int oh = o >> 3, oo = o & 7;
        double s = 0.0;
        for (int c = 0; c < NCH; c++)
            for (int q = 0; q < 2; q++)
                s += (double)g_pAtB[(((((size_t)i * NCH + c) * 2 + q) * 2 + oh) * 8 + oo) * 12 + k];
        sAtB[k][o] = s;
    }
    for (int p = t; p < 56; p += 128) {
        double s = 0.0;
        for (int c = 0; c < MCH; c++)
            s += (double)g_pMom[((size_t)i * MCH + c) * 56 + p];
        sS[p] = s;
    }
    __syncthreads();

    if (t < 66) {
        int p = t, r = 0;
        while (p >= KB - r) { p -= KB - r; r++; }
        int cc = r + p;
        double val = 0.0;
        for (int j = 0; j < 8; j++) {
            int a = r - j, b = cc - j;
            if (a >= 0 && a < 4 && b >= 0 && b < 4) {
                for (int p1 = 0; p1 < 4; p1++)
                    for (int q1 = 0; q1 < 4; q1++)
                        val += CAD[a][p1] * CAD[b][q1] * sS[j * 7 + p1 + q1];
            }
        }
        sAtA[t] = val / 36.0;
    }
    __syncthreads();

    if (t == 0) {
        for (int j = 0; j < KB; j++) {
            double d = sAtA[tidx(j, j)];
            for (int m = 0; m < j; m++) { double v = sL[tidx(m, j)]; d -= v * v; }
            d = sqrt(d);
            sL[tidx(j, j)] = d;
            double inv = 1.0 / d;
            for (int r = j + 1; r < KB; r++) {
                double s = sAtA[tidx(j, r)];
                for (int m = 0; m < j; m++) s -= sL[tidx(m, r)] * sL[tidx(m, j)];
                sL[tidx(j, r)] = s * inv;
            }
        }
    }
    __syncthreads();

    if (t < OUT_F) {
        const int o = t;
        double z[KB], X[KB];
        for (int r = 0; r < KB; r++) {
            double s = sAtB[r][o];
            for (int m = 0; m < r; m++) s -= sL[tidx(m, r)] * z[m];
            z[r] = s / sL[tidx(r, r)];
        }
        for (int r = KB - 1; r >= 0; r--) {
            double s = z[r];
            for (int m = r + 1; m < KB; m++) s -= sL[tidx(r, m)] * X[m];
            X[r] = s / sL[tidx(r, r)];
            out[(size_t)o * (IN_F * KB) + i * KB + r] = (float)X[r];
        }
    }
}

extern "C" void kernel_launch(void* const* d_in, const int* in_sizes, int n_in,
                              void* d_out, int out_size) {
    const float* x = (const float*)d_in[0];
    const float* y = (const float*)d_in[1];
    (void)n_in; (void)out_size;
    float* out = (float*)d_out;
    int N = in_sizes[0] / IN_F;

    cudaFuncSetAttribute(accum_kernel,
                         cudaFuncAttributeMaxDynamicSharedMemorySize,
                         SMEM_FLOATS * (int)sizeof(float));

    dim3 tgrid((N + 31) / 32, IN_F / 32);
    transpose_kernel<<<tgrid, dim3(32, 8)>>>(x, N);

    moments_kernel<<<dim3(MCH, IN_F), 256>>>(N);

    accum_kernel<<<dim3(NCH, 32), 256, SMEM_FLOATS * (int)sizeof(float)>>>(y, N);

    solve_kernel<<<IN_F, 128>>>(out);
}